// round 10
// baseline (speedup 1.0000x reference)
#include <cuda_runtime.h>

// Attention_2362232013200 — B=256, S=196, D=2048, H=512, all fp32.
// R6: k1 back to 64x64 tile / 4x4 microtile (512 blocks -> occupancy), FFMA2
//     swap-trick; __ldcs streaming on big single-pass reads; k4 unroll x4.

typedef unsigned long long ull;

constexpr int B = 256;
constexpr int S = 196;
constexpr int D = 2048;
constexpr int H = 512;
constexpr int KS = 16;          // split-K factor
constexpr int KC = D / KS;      // 128 K per split
constexpr int BK = 16;

// ---- scratch (device globals; no allocations allowed) ----
__device__ __align__(16) float g_part[KS * B * H];   // 8 MB split-K partials
__device__ __align__(16) float g_weight[B * S];      // [B,S]

__device__ __forceinline__ float tanh_approx(float x) {
    float r;
    asm("tanh.approx.f32 %0, %1;" : "=f"(r) : "f"(x));
    return r;
}
__device__ __forceinline__ ull pack2(float lo, float hi) {
    ull r; asm("mov.b64 %0, {%1, %2};" : "=l"(r) : "f"(lo), "f"(hi)); return r;
}
__device__ __forceinline__ void unpack2(ull v, float& lo, float& hi) {
    asm("mov.b64 {%0, %1}, %2;" : "=f"(lo), "=f"(hi) : "l"(v));
}
__device__ __forceinline__ ull swap2(ull v) {
    float lo, hi; unpack2(v, lo, hi); return pack2(hi, lo);
}
__device__ __forceinline__ void ffma2(ull& acc, ull a, ull b) {
    asm("fma.rn.f32x2 %0, %1, %2, %0;" : "+l"(acc) : "l"(a), "l"(b));
}

// ---------------------------------------------------------------------------
// K1: split-K SGEMM partials. part[z][b][h] = sum_{k in chunk} h[b,k]*W[h,k]
// BM=BN=64, BK=16, 256 threads, 4x4 microtile via FFMA2 pairs (swap trick).
// accd[mp][np] = (c[2mp][2np],   c[2mp+1][2np+1])
// accx[mp][np] = (c[2mp+1][2np], c[2mp][2np+1])
// Grid: (256/64, 512/64, KS) = (4, 8, 16) = 512 blocks -> 3.5 blocks/SM.
// ---------------------------------------------------------------------------
__global__ __launch_bounds__(256) void k1_gemm(const float* __restrict__ A,
                                               const float* __restrict__ Wm) {
    __shared__ __align__(16) float As[BK][68];   // [k][m], padded
    __shared__ __align__(16) float Bs[BK][68];   // [k][n], padded

    const int bm = blockIdx.x * 64;
    const int bn = blockIdx.y * 64;
    const int k0 = blockIdx.z * KC;

    const int tid = threadIdx.x;
    const int tx = tid & 15;          // n-group (4 wide)
    const int ty = tid >> 4;          // m-group (4 wide)

    const int r0 = tid >> 2;          // loader row 0..63
    const int ko = (tid & 3) * 4;     // loader k offset 0,4,8,12

    const float* Ap = A  + (size_t)(bm + r0) * D + k0 + ko;
    const float* Bp = Wm + (size_t)(bn + r0) * D + k0 + ko;

    ull accd[2][2] = {};
    ull accx[2][2] = {};

    for (int kt = 0; kt < KC / BK; ++kt) {
        float4 av = *(const float4*)(Ap + kt * BK);
        float4 bv = *(const float4*)(Bp + kt * BK);
        if (kt) __syncthreads();
        As[ko + 0][r0] = av.x; As[ko + 1][r0] = av.y;
        As[ko + 2][r0] = av.z; As[ko + 3][r0] = av.w;
        Bs[ko + 0][r0] = bv.x; Bs[ko + 1][r0] = bv.y;
        Bs[ko + 2][r0] = bv.z; Bs[ko + 3][r0] = bv.w;
        __syncthreads();
#pragma unroll
        for (int kk = 0; kk < BK; ++kk) {
            const ull* ap = (const ull*)&As[kk][ty * 4];
            const ull* bp = (const ull*)&Bs[kk][tx * 4];
            ull pa0 = ap[0], pa1 = ap[1];
            ull pb0 = bp[0], pb1 = bp[1];
            ull sa0 = swap2(pa0), sa1 = swap2(pa1);
            ffma2(accd[0][0], pa0, pb0); ffma2(accx[0][0], sa0, pb0);
            ffma2(accd[0][1], pa0, pb1); ffma2(accx[0][1], sa0, pb1);
            ffma2(accd[1][0], pa1, pb0); ffma2(accx[1][0], sa1, pb0);
            ffma2(accd[1][1], pa1, pb1); ffma2(accx[1][1], sa1, pb1);
        }
    }

    float* po = g_part + (size_t)blockIdx.z * (B * H) +
                (size_t)(bm + ty * 4) * H + bn + tx * 4;
#pragma unroll
    for (int mp = 0; mp < 2; ++mp) {
        float e0[4], e1[4];
#pragma unroll
        for (int np = 0; np < 2; ++np) {
            float dlo, dhi, xlo, xhi;
            unpack2(accd[mp][np], dlo, dhi);
            unpack2(accx[mp][np], xlo, xhi);
            e0[2 * np] = dlo; e0[2 * np + 1] = xhi;   // row 2mp
            e1[2 * np] = xlo; e1[2 * np + 1] = dhi;   // row 2mp+1
        }
        *(float4*)(po + (size_t)(2 * mp) * H) =
            make_float4(e0[0], e0[1], e0[2], e0[3]);
        *(float4*)(po + (size_t)(2 * mp + 1) * H) =
            make_float4(e1[0], e1[1], e1[2], e1[3]);
    }
}

// ---------------------------------------------------------------------------
// K2: fused split-K reduce + scores + softmax + mask renorm. One block per b.
//   ah[h] = bias[h] + sum_z part[z][b][h]
//   scores[s] = sum_h w_alpha[h]*tanh(p[b,s,h] + ah[h])   (b_alpha cancels)
//   weight = (softmax(scores)*mask) / sum(...)
// 256 threads; each warp handles rows s and s+98 together (2x MLP).
// ---------------------------------------------------------------------------
__global__ __launch_bounds__(256) void k2_fused(const float* __restrict__ p_att,
                                                const float* __restrict__ w_alpha,
                                                const float* __restrict__ bias,
                                                const float* __restrict__ mask) {
    __shared__ __align__(16) float ah[H];
    __shared__ __align__(16) float wa[H];
    __shared__ float sc[256];
    __shared__ float red[256];

    const int b = blockIdx.x;
    const int tid = threadIdx.x;

    for (int i = tid; i < H; i += 256) {
        float s = bias[i];
#pragma unroll
        for (int z = 0; z < KS; ++z) s += g_part[(size_t)z * (B * H) + b * H + i];
        ah[i] = s;
        wa[i] = w_alpha[i];
    }
    if (tid >= S) sc[tid] = -1e30f;        // pad tail for max-reduce
    __syncthreads();

    const int w = tid >> 5, l = tid & 31;

    for (int s = w; s < 98; s += 8) {       // pairs (s, s+98) cover 0..195
        const float4* pp0 = (const float4*)(p_att + (size_t)(b * S + s) * H);
        const float4* pp1 = (const float4*)(p_att + (size_t)(b * S + s + 98) * H);
        float acc0 = 0.f, acc1 = 0.f;
#pragma unroll
        for (int j = 0; j < 4; ++j) {
            const int hi = j * 32 + l;               // float4 index into H/4
            float4 p0 = __ldcs(pp0 + hi);
            float4 p1 = __ldcs(pp1 + hi);
            float4 a4 = *(const float4*)&ah[hi * 4];
            float4 w4 = *(const float4*)&wa[hi * 4];
            acc0 += w4.x * tanh_approx(p0.x + a4.x);
            acc0 += w4.y * tanh_approx(p0.y + a4.y);
            acc0 += w4.z * tanh_approx(p0.z + a4.z);
            acc0 += w4.w * tanh_approx(p0.w + a4.w);
            acc1 += w4.x * tanh_approx(p1.x + a4.x);
            acc1 += w4.y * tanh_approx(p1.y + a4.y);
            acc1 += w4.z * tanh_approx(p1.z + a4.z);
            acc1 += w4.w * tanh_approx(p1.w + a4.w);
        }
#pragma unroll
        for (int o = 16; o; o >>= 1) {
            acc0 += __shfl_xor_sync(0xFFFFFFFFu, acc0, o);
            acc1 += __shfl_xor_sync(0xFFFFFFFFu, acc1, o);
        }
        if (l == 0) { sc[s] = acc0; sc[s + 98] = acc1; }
    }
    __syncthreads();

    // block softmax over sc[0..255] (tail = -1e30)
    red[tid] = sc[tid]; __syncthreads();
    for (int o = 128; o; o >>= 1) {
        if (tid < o) red[tid] = fmaxf(red[tid], red[tid + o]);
        __syncthreads();
    }
    const float mx = red[0]; __syncthreads();

    // weight = e*mask / sum(e*mask): softmax denom cancels with renorm denom
    float wgt = (tid < S) ? __expf(sc[tid] - mx) * mask[b * S + tid] : 0.f;
    red[tid] = wgt; __syncthreads();
    for (int o = 128; o; o >>= 1) {
        if (tid < o) red[tid] += red[tid + o];
        __syncthreads();
    }
    const float inv = 1.f / red[0];
    if (tid < S) g_weight[b * S + tid] = wgt * inv;
}

// ---------------------------------------------------------------------------
// K4: att_res[b,d] = sum_s weight[b,s] * att_feats[b,s,d]
// Grid (B, 2); 256 threads; thread owns one float4; s unrolled x4 with 4
// independent accumulators (16 outstanding loads); streaming loads.
// ---------------------------------------------------------------------------
__global__ __launch_bounds__(256, 1) void k4_wsum(const float* __restrict__ feats,
                                                  float* __restrict__ out) {
    __shared__ float ws[S];
    const int b = blockIdx.x;
    const int dbase = blockIdx.y * 1024 + threadIdx.x * 4;

    if (threadIdx.x < S) ws[threadIdx.x] = g_weight[b * S + threadIdx.x];
    __syncthreads();

    const float4* fp = (const float4*)(feats + (size_t)b * S * D + dbase);
    float4 acc0 = make_float4(0.f, 0.f, 0.f, 0.f);
    float4 acc1 = make_float4(0.f, 0.f, 0.f, 0.f);
    float4 acc2 = make_float4(0.f, 0.f, 0.f, 0.f);
    float4 acc3 = make_float4(0.f, 0.f, 0.f, 0.f);
#pragma unroll 2
    for (int s = 0; s < S; s += 4) {        // S = 196 = 4*49
        float4 f0 = __ldcs(fp + (size_t)(s + 0) * (D / 4));
        float4 f1 = __ldcs(fp + (size_t)(s + 1) * (D / 4));
        float4 f2 = __ldcs(fp + (size_t)(s + 2) * (D / 4));
        float4 f3 = __ldcs(fp + (size_t)(s + 3) * (D / 4));
        const float w0 = ws[s], w1 = ws[s + 1];
        const float w2 = ws[s + 2], w3 = ws[s + 3];
        acc0.x += w0 * f0.x; acc0.y += w0 * f0.y;
        acc0.z += w0 * f0.z; acc0.w += w0 * f0.w;
        acc1.x += w1 * f1.x; acc1.y += w1 * f1.y;
        acc1.z += w1 * f1.z; acc1.w += w1 * f1.w;
        acc2.x += w2 * f2.x; acc2.y += w2 * f2.y;
        acc2.z += w2 * f2.z; acc2.w += w2 * f2.w;
        acc3.x += w3 * f3.x; acc3.y += w3 * f3.y;
        acc3.z += w3 * f3.z; acc3.w += w3 * f3.w;
    }
    *(float4*)(out + (size_t)b * D + dbase) =
        make_float4(acc0.x + acc1.x + acc2.x + acc3.x,
                    acc0.y + acc1.y + acc2.y + acc3.y,
                    acc0.z + acc1.z + acc2.z + acc3.z,
                    acc0.w + acc1.w + acc2.w + acc3.w);
}

// ---------------------------------------------------------------------------
extern "C" void kernel_launch(void* const* d_in, const int* in_sizes, int n_in,
                              void* d_out, int out_size) {
    const float* h         = (const float*)d_in[0];   // [B,D]
    const float* att_feats = (const float*)d_in[1];   // [B,S,D]
    const float* p_att     = (const float*)d_in[2];   // [B,S,H]
    const float* mask      = (const float*)d_in[3];   // [B,S]
    const float* W         = (const float*)d_in[4];   // [H,D]
    const float* b_h2att   = (const float*)d_in[5];   // [H]
    const float* w_alpha   = (const float*)d_in[6];   // [H]
    // d_in[7] = b_alpha: cancels in softmax, unused.
    float* out = (float*)d_out;                        // [B,D]

    k1_gemm <<<dim3(4, 8, KS), 256>>>(h, W);
    k2_fused<<<dim3(B), 256>>>(p_att, w_alpha, b_h2att, mask);
    k4_wsum <<<dim3(B, 2), 256>>>(att_feats, out);
}

// round 11
// speedup vs baseline: 1.1074x; 1.1074x over previous
#include <cuda_runtime.h>

// Attention_2362232013200 — B=256, S=196, D=2048, H=512, all fp32.
// R11: k1 = 128x64 tile, 8x8 microtile (1 B smem / MAC), 128 threads,
//      launch_bounds(128,4) -> 16 warps/SM. k2/k4 reverted to the 112.7us
//      versions (no __ldcs, k4 x2 dual-accumulator).

typedef unsigned long long ull;

constexpr int B = 256;
constexpr int S = 196;
constexpr int D = 2048;
constexpr int H = 512;
constexpr int KS = 16;          // split-K factor
constexpr int KC = D / KS;      // 128 K per split
constexpr int BK = 16;

// ---- scratch (device globals; no allocations allowed) ----
__device__ __align__(16) float g_part[KS * B * H];   // 8 MB split-K partials
__device__ __align__(16) float g_weight[B * S];      // [B,S]

__device__ __forceinline__ float tanh_approx(float x) {
    float r;
    asm("tanh.approx.f32 %0, %1;" : "=f"(r) : "f"(x));
    return r;
}
__device__ __forceinline__ ull pack2(float lo, float hi) {
    ull r; asm("mov.b64 %0, {%1, %2};" : "=l"(r) : "f"(lo), "f"(hi)); return r;
}
__device__ __forceinline__ void unpack2(ull v, float& lo, float& hi) {
    asm("mov.b64 {%0, %1}, %2;" : "=f"(lo), "=f"(hi) : "l"(v));
}
__device__ __forceinline__ ull swap2(ull v) {
    float lo, hi; unpack2(v, lo, hi); return pack2(hi, lo);
}
__device__ __forceinline__ void ffma2(ull& acc, ull a, ull b) {
    asm("fma.rn.f32x2 %0, %1, %2, %0;" : "+l"(acc) : "l"(a), "l"(b));
}

// ---------------------------------------------------------------------------
// K1: split-K SGEMM partials. part[z][b][h] = sum_{k in chunk} h[b,k]*W[h,k]
// BM=128, BN=64, BK=16. 128 threads, 8x8 microtile via FFMA2 swap trick:
//   accd[mp][np] = (c[2mp][2np],   c[2mp+1][2np+1])
//   accx[mp][np] = (c[2mp+1][2np], c[2mp][2np+1])
// Thread (ty,tx) with ty=tid>>3 (16 m-groups), tx=tid&7 (8 n-groups).
// Grid: (256/128, 512/64, KS) = (2, 8, 16) = 256 blocks, 4 resident/SM.
// ---------------------------------------------------------------------------
__global__ __launch_bounds__(128, 4) void k1_gemm(const float* __restrict__ A,
                                                  const float* __restrict__ Wm) {
    __shared__ __align__(16) float As[BK][132];   // [k][m], padded
    __shared__ __align__(16) float Bs[BK][68];    // [k][n], padded

    const int bm = blockIdx.x * 128;
    const int bn = blockIdx.y * 64;
    const int k0 = blockIdx.z * KC;

    const int tid = threadIdx.x;
    const int tx = tid & 7;           // n-group (8 wide)
    const int ty = tid >> 3;          // m-group (8 wide)

    const int r0 = tid >> 2;          // loader row 0..31
    const int ko = (tid & 3) * 4;     // loader k offset 0,4,8,12

    const float* Ap = A  + (size_t)(bm + r0) * D + k0 + ko;
    const float* Bp = Wm + (size_t)(bn + r0) * D + k0 + ko;

    ull accd[4][4] = {};
    ull accx[4][4] = {};

    for (int kt = 0; kt < KC / BK; ++kt) {
        // A: rows r0, r0+32, r0+64, r0+96 ; B: rows r0, r0+32
        float4 a0 = *(const float4*)(Ap + kt * BK);
        float4 a1 = *(const float4*)(Ap + kt * BK + (size_t)32 * D);
        float4 a2 = *(const float4*)(Ap + kt * BK + (size_t)64 * D);
        float4 a3 = *(const float4*)(Ap + kt * BK + (size_t)96 * D);
        float4 b0 = *(const float4*)(Bp + kt * BK);
        float4 b1 = *(const float4*)(Bp + kt * BK + (size_t)32 * D);
        if (kt) __syncthreads();
        As[ko + 0][r0]      = a0.x; As[ko + 1][r0]      = a0.y;
        As[ko + 2][r0]      = a0.z; As[ko + 3][r0]      = a0.w;
        As[ko + 0][r0 + 32] = a1.x; As[ko + 1][r0 + 32] = a1.y;
        As[ko + 2][r0 + 32] = a1.z; As[ko + 3][r0 + 32] = a1.w;
        As[ko + 0][r0 + 64] = a2.x; As[ko + 1][r0 + 64] = a2.y;
        As[ko + 2][r0 + 64] = a2.z; As[ko + 3][r0 + 64] = a2.w;
        As[ko + 0][r0 + 96] = a3.x; As[ko + 1][r0 + 96] = a3.y;
        As[ko + 2][r0 + 96] = a3.z; As[ko + 3][r0 + 96] = a3.w;
        Bs[ko + 0][r0]      = b0.x; Bs[ko + 1][r0]      = b0.y;
        Bs[ko + 2][r0]      = b0.z; Bs[ko + 3][r0]      = b0.w;
        Bs[ko + 0][r0 + 32] = b1.x; Bs[ko + 1][r0 + 32] = b1.y;
        Bs[ko + 2][r0 + 32] = b1.z; Bs[ko + 3][r0 + 32] = b1.w;
        __syncthreads();
#pragma unroll
        for (int kk = 0; kk < BK; ++kk) {
            const ull* ap = (const ull*)&As[kk][ty * 8];
            const ull* bp = (const ull*)&Bs[kk][tx * 8];
            ull pa[4], pb[4], sa[4];
#pragma unroll
            for (int i = 0; i < 4; ++i) { pa[i] = ap[i]; pb[i] = bp[i]; }
#pragma unroll
            for (int i = 0; i < 4; ++i) sa[i] = swap2(pa[i]);
#pragma unroll
            for (int np = 0; np < 4; ++np)
#pragma unroll
                for (int mp = 0; mp < 4; ++mp) {
                    ffma2(accd[mp][np], pa[mp], pb[np]);
                    ffma2(accx[mp][np], sa[mp], pb[np]);
                }
        }
    }

    float* po = g_part + (size_t)blockIdx.z * (B * H) +
                (size_t)(bm + ty * 8) * H + bn + tx * 8;
#pragma unroll
    for (int mp = 0; mp < 4; ++mp) {
        float e0[8], e1[8];
#pragma unroll
        for (int np = 0; np < 4; ++np) {
            float dlo, dhi, xlo, xhi;
            unpack2(accd[mp][np], dlo, dhi);
            unpack2(accx[mp][np], xlo, xhi);
            e0[2 * np] = dlo; e0[2 * np + 1] = xhi;   // row 2mp
            e1[2 * np] = xlo; e1[2 * np + 1] = dhi;   // row 2mp+1
        }
        float* r0p = po + (size_t)(2 * mp) * H;
        float* r1p = po + (size_t)(2 * mp + 1) * H;
        *(float4*)(r0p)     = make_float4(e0[0], e0[1], e0[2], e0[3]);
        *(float4*)(r0p + 4) = make_float4(e0[4], e0[5], e0[6], e0[7]);
        *(float4*)(r1p)     = make_float4(e1[0], e1[1], e1[2], e1[3]);
        *(float4*)(r1p + 4) = make_float4(e1[4], e1[5], e1[6], e1[7]);
    }
}

// ---------------------------------------------------------------------------
// K2: fused split-K reduce + scores + softmax + mask renorm. One block per b.
//   ah[h] = bias[h] + sum_z part[z][b][h]
//   scores[s] = sum_h w_alpha[h]*tanh(p[b,s,h] + ah[h])   (b_alpha cancels)
//   weight = (softmax(scores)*mask) / sum(...)
// 256 threads; each warp handles rows s and s+98 together (2x MLP).
// ---------------------------------------------------------------------------
__global__ __launch_bounds__(256) void k2_fused(const float* __restrict__ p_att,
                                                const float* __restrict__ w_alpha,
                                                const float* __restrict__ bias,
                                                const float* __restrict__ mask) {
    __shared__ __align__(16) float ah[H];
    __shared__ __align__(16) float wa[H];
    __shared__ float sc[256];
    __shared__ float red[256];

    const int b = blockIdx.x;
    const int tid = threadIdx.x;

    for (int i = tid; i < H; i += 256) {
        float s = bias[i];
#pragma unroll
        for (int z = 0; z < KS; ++z) s += g_part[(size_t)z * (B * H) + b * H + i];
        ah[i] = s;
        wa[i] = w_alpha[i];
    }
    if (tid >= S) sc[tid] = -1e30f;        // pad tail for max-reduce
    __syncthreads();

    const int w = tid >> 5, l = tid & 31;

    for (int s = w; s < 98; s += 8) {       // pairs (s, s+98) cover 0..195
        const float4* pp0 = (const float4*)(p_att + (size_t)(b * S + s) * H);
        const float4* pp1 = (const float4*)(p_att + (size_t)(b * S + s + 98) * H);
        float acc0 = 0.f, acc1 = 0.f;
#pragma unroll
        for (int j = 0; j < 4; ++j) {
            const int hi = j * 32 + l;               // float4 index into H/4
            float4 p0 = pp0[hi];
            float4 p1 = pp1[hi];
            float4 a4 = *(const float4*)&ah[hi * 4];
            float4 w4 = *(const float4*)&wa[hi * 4];
            acc0 += w4.x * tanh_approx(p0.x + a4.x);
            acc0 += w4.y * tanh_approx(p0.y + a4.y);
            acc0 += w4.z * tanh_approx(p0.z + a4.z);
            acc0 += w4.w * tanh_approx(p0.w + a4.w);
            acc1 += w4.x * tanh_approx(p1.x + a4.x);
            acc1 += w4.y * tanh_approx(p1.y + a4.y);
            acc1 += w4.z * tanh_approx(p1.z + a4.z);
            acc1 += w4.w * tanh_approx(p1.w + a4.w);
        }
#pragma unroll
        for (int o = 16; o; o >>= 1) {
            acc0 += __shfl_xor_sync(0xFFFFFFFFu, acc0, o);
            acc1 += __shfl_xor_sync(0xFFFFFFFFu, acc1, o);
        }
        if (l == 0) { sc[s] = acc0; sc[s + 98] = acc1; }
    }
    __syncthreads();

    // block softmax over sc[0..255] (tail = -1e30)
    red[tid] = sc[tid]; __syncthreads();
    for (int o = 128; o; o >>= 1) {
        if (tid < o) red[tid] = fmaxf(red[tid], red[tid + o]);
        __syncthreads();
    }
    const float mx = red[0]; __syncthreads();

    // weight = e*mask / sum(e*mask): softmax denom cancels with renorm denom
    float wgt = (tid < S) ? __expf(sc[tid] - mx) * mask[b * S + tid] : 0.f;
    red[tid] = wgt; __syncthreads();
    for (int o = 128; o; o >>= 1) {
        if (tid < o) red[tid] += red[tid + o];
        __syncthreads();
    }
    const float inv = 1.f / red[0];
    if (tid < S) g_weight[b * S + tid] = wgt * inv;
}

// ---------------------------------------------------------------------------
// K4: att_res[b,d] = sum_s weight[b,s] * att_feats[b,s,d]
// Grid (B, 2); 256 threads; thread owns one float4; s unrolled x2, dual acc.
// ---------------------------------------------------------------------------
__global__ __launch_bounds__(256, 1) void k4_wsum(const float* __restrict__ feats,
                                                  float* __restrict__ out) {
    __shared__ float ws[S];
    const int b = blockIdx.x;
    const int dbase = blockIdx.y * 1024 + threadIdx.x * 4;

    if (threadIdx.x < S) ws[threadIdx.x] = g_weight[b * S + threadIdx.x];
    __syncthreads();

    const float4* fp = (const float4*)(feats + (size_t)b * S * D + dbase);
    float4 acc0 = make_float4(0.f, 0.f, 0.f, 0.f);
    float4 acc1 = make_float4(0.f, 0.f, 0.f, 0.f);
#pragma unroll 4
    for (int s = 0; s < S; s += 2) {
        float4 f0 = fp[(size_t)s * (D / 4)];
        float4 f1 = fp[(size_t)(s + 1) * (D / 4)];
        const float w0 = ws[s];
        const float w1 = ws[s + 1];
        acc0.x += w0 * f0.x; acc0.y += w0 * f0.y;
        acc0.z += w0 * f0.z; acc0.w += w0 * f0.w;
        acc1.x += w1 * f1.x; acc1.y += w1 * f1.y;
        acc1.z += w1 * f1.z; acc1.w += w1 * f1.w;
    }
    *(float4*)(out + (size_t)b * D + dbase) =
        make_float4(acc0.x + acc1.x, acc0.y + acc1.y,
                    acc0.z + acc1.z, acc0.w + acc1.w);
}

// ---------------------------------------------------------------------------
extern "C" void kernel_launch(void* const* d_in, const int* in_sizes, int n_in,
                              void* d_out, int out_size) {
    const float* h         = (const float*)d_in[0];   // [B,D]
    const float* att_feats = (const float*)d_in[1];   // [B,S,D]
    const float* p_att     = (const float*)d_in[2];   // [B,S,H]
    const float* mask      = (const float*)d_in[3];   // [B,S]
    const float* W         = (const float*)d_in[4];   // [H,D]
    const float* b_h2att   = (const float*)d_in[5];   // [H]
    const float* w_alpha   = (const float*)d_in[6];   // [H]
    // d_in[7] = b_alpha: cancels in softmax, unused.
    float* out = (float*)d_out;                        // [B,D]

    k1_gemm <<<dim3(2, 8, KS), 128>>>(h, W);
    k2_fused<<<dim3(B), 256>>>(p_att, w_alpha, b_h2att, mask);
    k4_wsum <<<dim3(B, 2), 256>>>(att_feats, out);
}